// round 10
// baseline (speedup 1.0000x reference)
#include <cuda_runtime.h>
#include <cuda_bf16.h>
#include <cstdint>
#include <cstddef>

#define DINLINE __device__ __forceinline__

namespace {
constexpr int E       = 1024;
constexpr int KC      = 2048;
constexpr int MAXROWS = 32000;

constexpr int BM = 128;          // CTA rows
constexpr int BN = 128;          // CTA centroids
constexpr int BK = 64;           // k-chunk (64 bf16 = 128B row, SW128-friendly)
constexpr int NK = E / BK;       // 16
constexpr int NSTAGE = 3;
constexpr int GTHREADS = 256;    // 8 warps: 4(m) x 2(n), warp tile 32x64

constexpr int STAGE_BYTES = (BM + BN) * BK * 2;     // 32KB
constexpr int OFF_B       = BM * BK * 2;            // B tile after A within stage
constexpr int OFF_CNORM   = NSTAGE * STAGE_BYTES;   // 96KB
constexpr int GSMEM_TOTAL = OFF_CNORM + BN * 4;     // 98816

constexpr float MARGIN = 1.5f;   // 2*eps bound for bf16-gemm dist error
constexpr int   CPR    = 128;    // candidate slots per row (expected ~33 used)
}

// ---------------- device scratch --------------------------------------------
__device__ __nv_bfloat16 g_x_bf[MAXROWS * E];   // 64MB
__device__ __nv_bfloat16 g_c_bf[KC * E];        // 4MB
__device__ float         g_cnorm[KC];
__device__ float2        g_cand[(size_t)MAXROWS * CPR];  // {dist, idx-as-float-bits}
__device__ int           g_ccnt[MAXROWS];

// ---------------- helpers ----------------------------------------------------
DINLINE uint32_t smem_u32(const void* p) {
    uint32_t a;
    asm("{ .reg .u64 t; cvta.to.shared.u64 t, %1; cvt.u32.u64 %0, t; }"
        : "=r"(a) : "l"(p));
    return a;
}
DINLINE uint32_t sw128(uint32_t o) { return o ^ ((o >> 3) & 0x70); }

DINLINE void cp16(uint32_t dst, const void* src) {
    asm volatile("cp.async.cg.shared.global [%0], [%1], 16;"
                 :: "r"(dst), "l"(src) : "memory");
}
#define CP_COMMIT()      asm volatile("cp.async.commit_group;" ::: "memory")
#define CP_WAIT_GROUP(n) asm volatile("cp.async.wait_group %0;" :: "n"(n) : "memory")

DINLINE void ldm_x4(uint32_t& r0, uint32_t& r1, uint32_t& r2, uint32_t& r3,
                    uint32_t addr) {
    asm volatile("ldmatrix.sync.aligned.m8n8.x4.shared.b16 {%0,%1,%2,%3}, [%4];"
                 : "=r"(r0), "=r"(r1), "=r"(r2), "=r"(r3) : "r"(addr));
}
DINLINE void mma_bf16(float& d0, float& d1, float& d2, float& d3,
                      uint32_t a0, uint32_t a1, uint32_t a2, uint32_t a3,
                      uint32_t b0, uint32_t b1) {
    asm volatile("mma.sync.aligned.m16n8k16.row.col.f32.bf16.bf16.f32 "
                 "{%0,%1,%2,%3}, {%4,%5,%6,%7}, {%8,%9}, {%0,%1,%2,%3};"
                 : "+f"(d0), "+f"(d1), "+f"(d2), "+f"(d3)
                 : "r"(a0), "r"(a1), "r"(a2), "r"(a3), "r"(b0), "r"(b1));
}

// ---------------- prologue: fp32 -> bf16, centroid norms ---------------------
__global__ void tobf16_kernel(const float* __restrict__ src,
                              uint4* __restrict__ dst, int n8) {
    int i = blockIdx.x * blockDim.x + threadIdx.x;
    if (i >= n8) return;
    const float4* s4 = reinterpret_cast<const float4*>(src) + (size_t)i * 2;
    float4 a = s4[0], b = s4[1];
    float v[8] = {a.x, a.y, a.z, a.w, b.x, b.y, b.z, b.w};
    uint4 o;
    unsigned short* p = reinterpret_cast<unsigned short*>(&o);
    #pragma unroll
    for (int j = 0; j < 8; j++)
        p[j] = __bfloat16_as_ushort(__float2bfloat16(v[j]));
    dst[i] = o;
}

__global__ void cnorm_kernel(const float* __restrict__ cen) {
    const int k = blockIdx.x;
    const float* row = cen + (size_t)k * E;
    float s = 0.f;
    for (int e = threadIdx.x; e < E; e += blockDim.x) {
        float v = row[e];
        s = fmaf(v, v, s);
    }
    __shared__ float sm[8];
    #pragma unroll
    for (int off = 16; off > 0; off >>= 1) s += __shfl_down_sync(0xffffffffu, s, off);
    if ((threadIdx.x & 31) == 0) sm[threadIdx.x >> 5] = s;
    __syncthreads();
    if (threadIdx.x < 8) {
        s = sm[threadIdx.x];
        #pragma unroll
        for (int off = 4; off > 0; off >>= 1) s += __shfl_down_sync(0xffu, s, off);
        if (threadIdx.x == 0) g_cnorm[k] = s;
    }
}

// ---------------- GEMM + fused candidate-argmin epilogue ---------------------
DINLINE void fill_stage(int kt, int row0, int n0, int tid, uint32_t sbase) {
    const uint32_t soff = (uint32_t)(kt % NSTAGE) * STAGE_BYTES;
    const int r    = tid >> 1;          // 0..127 (row within tile)
    const int half = tid & 1;           // k bytes 0-63 or 64-127
    const int k0   = kt * BK + half * 32;   // element offset
    const __nv_bfloat16* xs = g_x_bf + (size_t)(row0 + r) * E + k0;
    const __nv_bfloat16* cs = g_c_bf + (size_t)(n0 + r) * E + k0;
    const uint32_t base = (uint32_t)r * 128u + (uint32_t)half * 64u;
    #pragma unroll
    for (int q = 0; q < 4; q++)
        cp16(sbase + soff + sw128(base + q * 16), xs + q * 8);
    #pragma unroll
    for (int q = 0; q < 4; q++)
        cp16(sbase + soff + OFF_B + sw128(base + q * 16), cs + q * 8);
}

__global__ void __launch_bounds__(GTHREADS, 2)
gemm_bf16_kernel() {
    extern __shared__ __align__(1024) char smem[];
    const uint32_t sbase = smem_u32(smem);
    const int tid  = threadIdx.x;
    const int lane = tid & 31;
    const int wid  = tid >> 5;
    const int wm   = wid & 3;           // warp m: 0..3 (32 rows each)
    const int wn   = wid >> 2;          // warp n: 0..1 (64 cols each)
    const int n0   = blockIdx.x * BN;
    const int row0 = blockIdx.y * BM;

    float* s_cnorm = reinterpret_cast<float*>(smem + OFF_CNORM);
    if (tid < BN) s_cnorm[tid] = g_cnorm[n0 + tid];

    float acc[2][8][4];
    #pragma unroll
    for (int mt = 0; mt < 2; mt++)
        #pragma unroll
        for (int nt = 0; nt < 8; nt++)
            #pragma unroll
            for (int v = 0; v < 4; v++) acc[mt][nt][v] = 0.f;

    fill_stage(0, row0, n0, tid, sbase); CP_COMMIT();
    fill_stage(1, row0, n0, tid, sbase); CP_COMMIT();

    // ldmatrix lane-address components
    const int lrow16 = lane & 15;       // row within 16
    const int lksel  = lane >> 4;       // 0: k 0-7, 1: k 8-15 (x16B)
    const int bgrp   = lane >> 3;       // B x4 group 0..3
    const int brow   = lane & 7;

    for (int kt = 0; kt < NK; kt++) {
        CP_WAIT_GROUP(1);          // stage kt resident
        __syncthreads();           // visibility + all reads of slot (kt-1) done

        const uint32_t sa = sbase + (uint32_t)(kt % NSTAGE) * STAGE_BYTES;
        const uint32_t sb = sa + OFF_B;

        // ---- preload slice-0 fragments FIRST (before cp.async fill issues) ----
        uint32_t bF[2][8][2];
        #pragma unroll
        for (int np = 0; np < 4; np++) {
            uint32_t n = (uint32_t)(wn * 64 + (np * 2 + (bgrp >> 1)) * 8 + brow);
            uint32_t addr = sb + sw128(n * 128u + (uint32_t)(bgrp & 1) * 16u);
            uint32_t r0, r1, r2, r3;
            ldm_x4(r0, r1, r2, r3, addr);
            bF[0][np * 2][0] = r0; bF[0][np * 2][1] = r1;
            bF[0][np * 2 + 1][0] = r2; bF[0][np * 2 + 1][1] = r3;
        }
        uint32_t aF0[2][4];
        #pragma unroll
        for (int mt = 0; mt < 2; mt++) {
            uint32_t r = (uint32_t)(wm * 32 + mt * 16 + lrow16);
            uint32_t addr = sa + sw128(r * 128u + (uint32_t)lksel * 16u);
            ldm_x4(aF0[mt][0], aF0[mt][1], aF0[mt][2], aF0[mt][3], addr);
        }

        // ---- now issue next stage's fill (won't delay the first MMAs) --------
        if (kt + 2 < NK) fill_stage(kt + 2, row0, n0, tid, sbase);
        CP_COMMIT();               // unconditional: uniform group accounting

        #pragma unroll
        for (int ks = 0; ks < 4; ks++) {
            const uint32_t kb = (uint32_t)ks * 32u;
            const int cur = ks & 1;

            uint32_t aF[2][4];
            if (ks == 0) {
                #pragma unroll
                for (int mt = 0; mt < 2; mt++)
                    #pragma unroll
                    for (int q = 0; q < 4; q++) aF[mt][q] = aF0[mt][q];
            } else {
                #pragma unroll
                for (int mt = 0; mt < 2; mt++) {
                    uint32_t r = (uint32_t)(wm * 32 + mt * 16 + lrow16);
                    uint32_t addr = sa + sw128(r * 128u + kb + (uint32_t)lksel * 16u);
                    ldm_x4(aF[mt][0], aF[mt][1], aF[mt][2], aF[mt][3], addr);
                }
            }
            if (ks < 3) {
                const uint32_t kbn = kb + 32u;
                #pragma unroll
                for (int np = 0; np < 4; np++) {
                    uint32_t n = (uint32_t)(wn * 64 + (np * 2 + (bgrp >> 1)) * 8 + brow);
                    uint32_t addr = sb + sw128(n * 128u + kbn + (uint32_t)(bgrp & 1) * 16u);
                    uint32_t r0, r1, r2, r3;
                    ldm_x4(r0, r1, r2, r3, addr);
                    bF[cur ^ 1][np * 2][0] = r0; bF[cur ^ 1][np * 2][1] = r1;
                    bF[cur ^ 1][np * 2 + 1][0] = r2; bF[cur ^ 1][np * 2 + 1][1] = r3;
                }
            }
            #pragma unroll
            for (int mt = 0; mt < 2; mt++)
                #pragma unroll
                for (int nt = 0; nt < 8; nt++)
                    mma_bf16(acc[mt][nt][0], acc[mt][nt][1],
                             acc[mt][nt][2], acc[mt][nt][3],
                             aF[mt][0], aF[mt][1], aF[mt][2], aF[mt][3],
                             bF[cur][nt][0], bF[cur][nt][1]);
        }
    }

    // ---- fused epilogue: per-row part-min + candidate append ----------------
    // Thread owns, per (mt, half): row = wm*32+mt*16+lr+half*8, 16 cols.
    // 4 lanes (same lr) cover the warp's 64 cols of that row.
    const int lr = lane >> 2;           // 0..7
    const int lc = (lane & 3) * 2;
    #pragma unroll
    for (int mt = 0; mt < 2; mt++) {
        #pragma unroll
        for (int half = 0; half < 2; half++) {
            const int row  = wm * 32 + mt * 16 + lr + half * 8;
            const int grow = row0 + row;
            float d[16];
            float mn = 3.4e38f;
            #pragma unroll
            for (int nt = 0; nt < 8; nt++) {
                const int col = wn * 64 + nt * 8 + lc;
                d[nt * 2 + 0] = fmaf(-2.f, acc[mt][nt][half * 2 + 0], s_cnorm[col]);
                d[nt * 2 + 1] = fmaf(-2.f, acc[mt][nt][half * 2 + 1], s_cnorm[col + 1]);
                mn = fminf(mn, fminf(d[nt * 2], d[nt * 2 + 1]));
            }
            // part-min across the 4 lanes sharing this row
            mn = fminf(mn, __shfl_xor_sync(0xffffffffu, mn, 1));
            mn = fminf(mn, __shfl_xor_sync(0xffffffffu, mn, 2));
            const float th = mn + MARGIN;
            #pragma unroll
            for (int nt = 0; nt < 8; nt++) {
                #pragma unroll
                for (int v = 0; v < 2; v++) {
                    const float dv = d[nt * 2 + v];
                    if (dv <= th) {
                        const int cidx = n0 + wn * 64 + nt * 8 + lc + v;
                        int p = atomicAdd(&g_ccnt[grow], 1);
                        if (p < CPR)
                            g_cand[(size_t)grow * CPR + p] =
                                make_float2(dv, __int_as_float(cidx));
                    }
                }
            }
        }
    }
}

// ---------------- refine: candidate scan + rare exact recheck ----------------
__global__ void __launch_bounds__(256)
refine_kernel(const float* __restrict__ x, const float* __restrict__ cen,
              float* __restrict__ out) {
    const int lane = threadIdx.x & 31;
    const int row  = blockIdx.x * 8 + (threadIdx.x >> 5);

    const int cnt = min(g_ccnt[row], CPR);
    const float2* cl = g_cand + (size_t)row * CPR;

    // min approx dist over candidates
    float m = 3.4e38f;
    for (int i = lane; i < cnt; i += 32) m = fminf(m, cl[i].x);
    #pragma unroll
    for (int o = 16; o > 0; o >>= 1)
        m = fminf(m, __shfl_xor_sync(0xffffffffu, m, o));
    const float th = m + MARGIN;

    // count qualifying; track single-winner fast path (min idx among qualifying)
    int nq = 0, solo = 0x7fffffff;
    for (int i = lane; i < cnt; i += 32) {
        if (cl[i].x <= th) { nq++; solo = min(solo, __float_as_int(cl[i].y)); }
    }
    #pragma unroll
    for (int o = 16; o > 0; o >>= 1) {
        nq   += __shfl_xor_sync(0xffffffffu, nq, o);
        solo  = min(solo, __shfl_xor_sync(0xffffffffu, solo, o));
    }

    if (nq == 1) {
        if (lane == 0) out[row] = (float)solo;
        return;
    }

    // exact fp32 recheck of all qualifying candidates (rare path)
    const float4* xr = reinterpret_cast<const float4*>(x + (size_t)row * E);
    float best_d = 3.4e38f;
    int   best_i = 0x7fffffff;
    for (int i = 0; i < cnt; i++) {
        float2 c = cl[i];                 // uniform: broadcast load
        if (c.x > th) continue;
        const int ci = __float_as_int(c.y);
        const float4* cr = reinterpret_cast<const float4*>(cen + (size_t)ci * E);
        float p = 0.f;
        #pragma unroll
        for (int j = 0; j < 8; j++) {
            float4 a = xr[lane + 32 * j];
            float4 b = cr[lane + 32 * j];
            p = fmaf(a.x, b.x, p); p = fmaf(a.y, b.y, p);
            p = fmaf(a.z, b.z, p); p = fmaf(a.w, b.w, p);
        }
        #pragma unroll
        for (int o = 16; o > 0; o >>= 1)
            p += __shfl_xor_sync(0xffffffffu, p, o);
        const float dd = fmaf(-2.f, p, g_cnorm[ci]);   // same in all lanes
        if (dd < best_d || (dd == best_d && ci < best_i)) { best_d = dd; best_i = ci; }
    }
    if (lane == 0) out[row] = (float)best_i;
}

// ---------------- launch ------------------------------------------------------
extern "C" void kernel_launch(void* const* d_in, const int* in_sizes, int n_in,
                              void* d_out, int out_size) {
    const float* a0 = (const float*)d_in[0];
    const float* a1 = (const float*)d_in[1];
    const float* x;
    const float* cen;
    if (in_sizes[0] >= in_sizes[1]) { x = a0; cen = a1; }
    else                            { x = a1; cen = a0; }

    float* out = (float*)d_out;
    const int nrows = out_size;                  // 32000

    __nv_bfloat16 *xb, *cb;
    void* ccnt;
    cudaGetSymbolAddress((void**)&xb, g_x_bf);
    cudaGetSymbolAddress((void**)&cb, g_c_bf);
    cudaGetSymbolAddress(&ccnt, g_ccnt);

    const int n8x = nrows * E / 8;
    tobf16_kernel<<<(n8x + 255) / 256, 256>>>(x, (uint4*)xb, n8x);
    const int n8c = KC * E / 8;
    tobf16_kernel<<<(n8c + 255) / 256, 256>>>(cen, (uint4*)cb, n8c);
    cnorm_kernel<<<KC, 256>>>(cen);
    cudaMemsetAsync(ccnt, 0, (size_t)nrows * sizeof(int));

    cudaFuncSetAttribute(gemm_bf16_kernel,
                         cudaFuncAttributeMaxDynamicSharedMemorySize, GSMEM_TOTAL);
    dim3 ggrid(KC / BN, nrows / BM);             // (16, 250)
    gemm_bf16_kernel<<<ggrid, GTHREADS, GSMEM_TOTAL>>>();

    refine_kernel<<<nrows / 8, 256>>>(x, cen, out);
}

// round 11
// speedup vs baseline: 1.0301x; 1.0301x over previous
#include <cuda_runtime.h>
#include <cuda_bf16.h>
#include <cuda_fp16.h>
#include <cstdint>
#include <cstddef>

#define DINLINE __device__ __forceinline__

namespace {
constexpr int E       = 1024;
constexpr int KC      = 2048;
constexpr int MAXROWS = 32000;

constexpr int BM = 128;          // CTA rows
constexpr int BN = 128;          // CTA centroids
constexpr int BK = 64;           // k-chunk (64 bf16 = 128B row, SW128-friendly)
constexpr int NK = E / BK;       // 16
constexpr int NSTAGE = 3;
constexpr int GTHREADS = 256;    // 8 warps: 4(m) x 2(n), warp tile 32x64

constexpr int STAGE_BYTES = (BM + BN) * BK * 2;     // 32KB
constexpr int OFF_B       = BM * BK * 2;            // B tile after A within stage
constexpr int OFF_CNORM   = NSTAGE * STAGE_BYTES;   // 96KB
constexpr int GSMEM_TOTAL = OFF_CNORM + BN * 4;     // 98816

constexpr float DOFF     = 1024.0f;  // subtract before fp16 store (centers range)
constexpr float MARGIN   = 1.5f;     // bf16-gemm err (<=1.0) + fp16 quant (2x0.25)
constexpr int   MAXCAND  = 128;

constexpr int XBLK = 2048;           // x elements converted per prologue block
}

// ---------------- device scratch --------------------------------------------
__device__ __nv_bfloat16 g_x_bf[MAXROWS * E];   // 64MB
__device__ __nv_bfloat16 g_c_bf[KC * E];        // 4MB
__device__ __align__(16) __half g_D[(size_t)MAXROWS * KC]; // 131MB dists - DOFF
__device__ float         g_cnorm[KC];

// ---------------- helpers ----------------------------------------------------
DINLINE uint32_t smem_u32(const void* p) {
    uint32_t a;
    asm("{ .reg .u64 t; cvta.to.shared.u64 t, %1; cvt.u32.u64 %0, t; }"
        : "=r"(a) : "l"(p));
    return a;
}
DINLINE uint32_t sw128(uint32_t o) { return o ^ ((o >> 3) & 0x70); }

DINLINE void cp16(uint32_t dst, const void* src) {
    asm volatile("cp.async.cg.shared.global [%0], [%1], 16;"
                 :: "r"(dst), "l"(src) : "memory");
}
#define CP_COMMIT()      asm volatile("cp.async.commit_group;" ::: "memory")
#define CP_WAIT_GROUP(n) asm volatile("cp.async.wait_group %0;" :: "n"(n) : "memory")

DINLINE void ldm_x4(uint32_t& r0, uint32_t& r1, uint32_t& r2, uint32_t& r3,
                    uint32_t addr) {
    asm volatile("ldmatrix.sync.aligned.m8n8.x4.shared.b16 {%0,%1,%2,%3}, [%4];"
                 : "=r"(r0), "=r"(r1), "=r"(r2), "=r"(r3) : "r"(addr));
}
DINLINE void mma_bf16(float& d0, float& d1, float& d2, float& d3,
                      uint32_t a0, uint32_t a1, uint32_t a2, uint32_t a3,
                      uint32_t b0, uint32_t b1) {
    asm volatile("mma.sync.aligned.m16n8k16.row.col.f32.bf16.bf16.f32 "
                 "{%0,%1,%2,%3}, {%4,%5,%6,%7}, {%8,%9}, {%0,%1,%2,%3};"
                 : "+f"(d0), "+f"(d1), "+f"(d2), "+f"(d3)
                 : "r"(a0), "r"(a1), "r"(a2), "r"(a3), "r"(b0), "r"(b1));
}

// ---------------- merged prologue: convert x + convert c + cnorm -------------
// blocks [0, nxb): convert XBLK x-elements each.
// blocks [nxb, nxb+KC): convert one centroid row each AND compute its norm.
__global__ void prologue_kernel(const float* __restrict__ x,
                                const float* __restrict__ cen, int nxb) {
    const int tid = threadIdx.x;
    if (blockIdx.x < nxb) {
        // x conversion: 256 threads x 8 elems
        const size_t base = (size_t)blockIdx.x * XBLK + (size_t)tid * 8;
        const float4* s4 = reinterpret_cast<const float4*>(x + base);
        float4 a = s4[0], b = s4[1];
        float v[8] = {a.x, a.y, a.z, a.w, b.x, b.y, b.z, b.w};
        uint4 o;
        unsigned short* p = reinterpret_cast<unsigned short*>(&o);
        #pragma unroll
        for (int j = 0; j < 8; j++)
            p[j] = __bfloat16_as_ushort(__float2bfloat16(v[j]));
        *reinterpret_cast<uint4*>(g_x_bf + base) = o;
    } else {
        // centroid row: convert 1024 elems + norm
        const int row = blockIdx.x - nxb;
        const float4 a = reinterpret_cast<const float4*>(cen + (size_t)row * E)[tid];
        float v[4] = {a.x, a.y, a.z, a.w};
        uint2 o;
        unsigned short* p = reinterpret_cast<unsigned short*>(&o);
        float s = 0.f;
        #pragma unroll
        for (int j = 0; j < 4; j++) {
            p[j] = __bfloat16_as_ushort(__float2bfloat16(v[j]));
            s = fmaf(v[j], v[j], s);
        }
        *reinterpret_cast<uint2*>(g_c_bf + (size_t)row * E + tid * 4) = o;

        __shared__ float sm[8];
        #pragma unroll
        for (int off = 16; off > 0; off >>= 1)
            s += __shfl_down_sync(0xffffffffu, s, off);
        if ((tid & 31) == 0) sm[tid >> 5] = s;
        __syncthreads();
        if (tid < 8) {
            s = sm[tid];
            #pragma unroll
            for (int off = 4; off > 0; off >>= 1)
                s += __shfl_down_sync(0xffu, s, off);
            if (tid == 0) g_cnorm[row] = s;
        }
    }
}

// ---------------- GEMM: D[m][n] = cnorm[n] - 2 * x_bf . c_bf - DOFF ----------
DINLINE void fill_stage(int kt, int row0, int n0, int tid, uint32_t sbase) {
    const uint32_t soff = (uint32_t)(kt % NSTAGE) * STAGE_BYTES;
    const int r    = tid >> 1;          // 0..127 (row within tile)
    const int half = tid & 1;           // k bytes 0-63 or 64-127
    const int k0   = kt * BK + half * 32;   // element offset
    const __nv_bfloat16* xs = g_x_bf + (size_t)(row0 + r) * E + k0;
    const __nv_bfloat16* cs = g_c_bf + (size_t)(n0 + r) * E + k0;
    const uint32_t base = (uint32_t)r * 128u + (uint32_t)half * 64u;
    #pragma unroll
    for (int q = 0; q < 4; q++)
        cp16(sbase + soff + sw128(base + q * 16), xs + q * 8);
    #pragma unroll
    for (int q = 0; q < 4; q++)
        cp16(sbase + soff + OFF_B + sw128(base + q * 16), cs + q * 8);
}

__global__ void __launch_bounds__(GTHREADS, 2)
gemm_bf16_kernel() {
    extern __shared__ __align__(1024) char smem[];
    const uint32_t sbase = smem_u32(smem);
    const int tid  = threadIdx.x;
    const int lane = tid & 31;
    const int wid  = tid >> 5;
    const int wm   = wid & 3;           // warp m: 0..3 (32 rows each)
    const int wn   = wid >> 2;          // warp n: 0..1 (64 cols each)
    const int n0   = blockIdx.x * BN;
    const int row0 = blockIdx.y * BM;

    float* s_cnorm = reinterpret_cast<float*>(smem + OFF_CNORM);
    if (tid < BN) s_cnorm[tid] = g_cnorm[n0 + tid];

    float acc[2][8][4];
    #pragma unroll
    for (int mt = 0; mt < 2; mt++)
        #pragma unroll
        for (int nt = 0; nt < 8; nt++)
            #pragma unroll
            for (int v = 0; v < 4; v++) acc[mt][nt][v] = 0.f;

    fill_stage(0, row0, n0, tid, sbase); CP_COMMIT();
    fill_stage(1, row0, n0, tid, sbase); CP_COMMIT();

    // ldmatrix lane-address components
    const int lrow16 = lane & 15;       // row within 16
    const int lksel  = lane >> 4;       // 0: k 0-7, 1: k 8-15 (x16B)
    const int bgrp   = lane >> 3;       // B x4 group 0..3
    const int brow   = lane & 7;

    for (int kt = 0; kt < NK; kt++) {
        CP_WAIT_GROUP(1);          // stage kt resident
        __syncthreads();           // visibility + all reads of slot (kt-1) done

        const uint32_t sa = sbase + (uint32_t)(kt % NSTAGE) * STAGE_BYTES;
        const uint32_t sb = sa + OFF_B;

        // ---- preload slice-0 fragments FIRST (before cp.async fill issues) ----
        uint32_t bF[2][8][2];
        #pragma unroll
        for (int np = 0; np < 4; np++) {
            uint32_t n = (uint32_t)(wn * 64 + (np * 2 + (bgrp >> 1)) * 8 + brow);
            uint32_t addr = sb + sw128(n * 128u + (uint32_t)(bgrp & 1) * 16u);
            uint32_t r0, r1, r2, r3;
            ldm_x4(r0, r1, r2, r3, addr);
            bF[0][np * 2][0] = r0; bF[0][np * 2][1] = r1;
            bF[0][np * 2 + 1][0] = r2; bF[0][np * 2 + 1][1] = r3;
        }
        uint32_t aF0[2][4];
        #pragma unroll
        for (int mt = 0; mt < 2; mt++) {
            uint32_t r = (uint32_t)(wm * 32 + mt * 16 + lrow16);
            uint32_t addr = sa + sw128(r * 128u + (uint32_t)lksel * 16u);
            ldm_x4(aF0[mt][0], aF0[mt][1], aF0[mt][2], aF0[mt][3], addr);
        }

        // ---- now issue next stage's fill (won't delay the first MMAs) --------
        if (kt + 2 < NK) fill_stage(kt + 2, row0, n0, tid, sbase);
        CP_COMMIT();               // unconditional: uniform group accounting

        #pragma unroll
        for (int ks = 0; ks < 4; ks++) {
            const uint32_t kb = (uint32_t)ks * 32u;
            const int cur = ks & 1;

            // A frags for this slice (ks=0 uses the preloaded ones)
            uint32_t aF[2][4];
            if (ks == 0) {
                #pragma unroll
                for (int mt = 0; mt < 2; mt++)
                    #pragma unroll
                    for (int q = 0; q < 4; q++) aF[mt][q] = aF0[mt][q];
            } else {
                #pragma unroll
                for (int mt = 0; mt < 2; mt++) {
                    uint32_t r = (uint32_t)(wm * 32 + mt * 16 + lrow16);
                    uint32_t addr = sa + sw128(r * 128u + kb + (uint32_t)lksel * 16u);
                    ldm_x4(aF[mt][0], aF[mt][1], aF[mt][2], aF[mt][3], addr);
                }
            }
            // prefetch B frags for next slice
            if (ks < 3) {
                const uint32_t kbn = kb + 32u;
                #pragma unroll
                for (int np = 0; np < 4; np++) {
                    uint32_t n = (uint32_t)(wn * 64 + (np * 2 + (bgrp >> 1)) * 8 + brow);
                    uint32_t addr = sb + sw128(n * 128u + kbn + (uint32_t)(bgrp & 1) * 16u);
                    uint32_t r0, r1, r2, r3;
                    ldm_x4(r0, r1, r2, r3, addr);
                    bF[cur ^ 1][np * 2][0] = r0; bF[cur ^ 1][np * 2][1] = r1;
                    bF[cur ^ 1][np * 2 + 1][0] = r2; bF[cur ^ 1][np * 2 + 1][1] = r3;
                }
            }
            #pragma unroll
            for (int mt = 0; mt < 2; mt++)
                #pragma unroll
                for (int nt = 0; nt < 8; nt++)
                    mma_bf16(acc[mt][nt][0], acc[mt][nt][1],
                             acc[mt][nt][2], acc[mt][nt][3],
                             aF[mt][0], aF[mt][1], aF[mt][2], aF[mt][3],
                             bF[cur][nt][0], bF[cur][nt][1]);
        }
    }

    // epilogue: dist-DOFF = cnorm[n] - 2*dot - DOFF, store fp16 pairs
    const int lr = lane >> 2;           // 0..7
    const int lc = (lane & 3) * 2;
    #pragma unroll
    for (int mt = 0; mt < 2; mt++) {
        #pragma unroll
        for (int half = 0; half < 2; half++) {   // v{0,1} vs v{2,3}: row +0/+8
            const int row = wm * 32 + mt * 16 + lr + half * 8;
            __half* drow = g_D + (size_t)(row0 + row) * KC + n0;
            #pragma unroll
            for (int nt = 0; nt < 8; nt++) {
                const int col = wn * 64 + nt * 8 + lc;
                float dx = fmaf(-2.f, acc[mt][nt][half * 2 + 0], s_cnorm[col])     - DOFF;
                float dy = fmaf(-2.f, acc[mt][nt][half * 2 + 1], s_cnorm[col + 1]) - DOFF;
                *reinterpret_cast<__half2*>(drow + col) = __floats2half2_rn(dx, dy);
            }
        }
    }
}

// ---------------- refine: scan row, exact fp32 recheck of candidates ---------
__global__ void __launch_bounds__(256)
refine_kernel(const float* __restrict__ x, const float* __restrict__ cen,
              float* __restrict__ out) {
    const int row = blockIdx.x;
    const int tid = threadIdx.x;
    const int lane = tid & 31;
    const int wid = tid >> 5;

    __shared__ float s_red[8];
    __shared__ int   s_cand[MAXCAND];
    __shared__ int   s_cnt;
    __shared__ float s_bmin;

    // pass 1: single uint4 load per thread = 8 contiguous halves
    const uint4 pack =
        reinterpret_cast<const uint4*>(g_D + (size_t)row * KC)[tid];
    float v[8];
    {
        const __half2* h2 = reinterpret_cast<const __half2*>(&pack);
        #pragma unroll
        for (int j = 0; j < 4; j++) {
            float2 f = __half22float2(h2[j]);
            v[j * 2 + 0] = f.x;
            v[j * 2 + 1] = f.y;
        }
    }
    float lmin = 3.4e38f;
    #pragma unroll
    for (int i = 0; i < 8; i++) lmin = fminf(lmin, v[i]);

    float m = lmin;
    #pragma unroll
    for (int off = 16; off > 0; off >>= 1)
        m = fminf(m, __shfl_down_sync(0xffffffffu, m, off));
    if (lane == 0) s_red[wid] = m;
    if (tid == 0) s_cnt = 0;
    __syncthreads();
    if (tid == 0) {
        float bm = s_red[0];
        #pragma unroll
        for (int w = 1; w < 8; w++) bm = fminf(bm, s_red[w]);
        s_bmin = bm;
    }
    __syncthreads();
    const float thresh = s_bmin + MARGIN;

    #pragma unroll
    for (int i = 0; i < 8; i++) {
        if (v[i] <= thresh) {
            int p = atomicAdd(&s_cnt, 1);
            if (p < MAXCAND) s_cand[p] = tid * 8 + i;
        }
    }
    __syncthreads();
    const int cnt = min(s_cnt, MAXCAND);

    // exact fp32 recheck of each candidate (whole block computes one dot)
    const float4* xr = reinterpret_cast<const float4*>(x + (size_t)row * E);
    float best_d = 3.4e38f;
    int   best_i = KC;
    for (int ci = 0; ci < cnt; ci++) {
        const int c = s_cand[ci];
        const float4* cr = reinterpret_cast<const float4*>(cen + (size_t)c * E);
        float4 xa = xr[tid];
        float4 ca = cr[tid];
        float p = xa.x * ca.x + xa.y * ca.y + xa.z * ca.z + xa.w * ca.w;
        #pragma unroll
        for (int off = 16; off > 0; off >>= 1)
            p += __shfl_down_sync(0xffffffffu, p, off);
        __syncthreads();          // protect s_red reuse
        if (lane == 0) s_red[wid] = p;
        __syncthreads();
        if (tid == 0) {
            float dot = 0.f;
            #pragma unroll
            for (int w = 0; w < 8; w++) dot += s_red[w];
            float d = fmaf(-2.f, dot, g_cnorm[c]);
            if (d < best_d || (d == best_d && c < best_i)) { best_d = d; best_i = c; }
        }
    }
    if (tid == 0) out[row] = (float)best_i;
}

// ---------------- launch ------------------------------------------------------
extern "C" void kernel_launch(void* const* d_in, const int* in_sizes, int n_in,
                              void* d_out, int out_size) {
    const float* a0 = (const float*)d_in[0];
    const float* a1 = (const float*)d_in[1];
    const float* x;
    const float* cen;
    if (in_sizes[0] >= in_sizes[1]) { x = a0; cen = a1; }
    else                            { x = a1; cen = a0; }

    float* out = (float*)d_out;
    const int nrows = out_size;                  // 32000

    // merged prologue: x-conversion blocks + centroid rows (convert + norm)
    const int nxb = nrows * E / XBLK;            // 16000
    prologue_kernel<<<nxb + KC, 256>>>(x, cen, nxb);

    cudaFuncSetAttribute(gemm_bf16_kernel,
                         cudaFuncAttributeMaxDynamicSharedMemorySize, GSMEM_TOTAL);
    dim3 ggrid(KC / BN, nrows / BM);             // (16, 250)
    gemm_bf16_kernel<<<ggrid, GTHREADS, GSMEM_TOTAL>>>();

    refine_kernel<<<nrows, 256>>>(x, cen, out);
}

// round 12
// speedup vs baseline: 1.0601x; 1.0291x over previous
#include <cuda_runtime.h>
#include <cuda_fp16.h>
#include <cstdint>
#include <cstddef>

#define DINLINE __device__ __forceinline__

namespace {
constexpr int E       = 1024;
constexpr int KC      = 2048;
constexpr int MAXROWS = 32000;

constexpr int BM = 256;          // CTA rows
constexpr int BN = 128;          // CTA centroids
constexpr int BK = 64;           // k-chunk (64 fp16 = 128B row, SW128-friendly)
constexpr int NK = E / BK;       // 16
constexpr int NSTAGE = 2;
constexpr int GTHREADS = 256;    // 8 warps: 4(m) x 2(n), warp tile 64x64

constexpr int STAGE_BYTES = (BM + BN) * BK * 2;     // 48KB
constexpr int OFF_B       = BM * BK * 2;            // 32KB: B after A in stage
constexpr int OFF_CNORM   = NSTAGE * STAGE_BYTES;   // 96KB
constexpr int GSMEM_TOTAL = OFF_CNORM + BN * 4;     // 98816 -> 2 CTAs/SM

constexpr float DOFF   = 2048.0f;  // center dists before fp16 store
constexpr float MARGIN = 10.0f;    // 2*eps: fp16-acc chain + fp16 quant
constexpr int   CAP    = 128;      // candidate cap per row

constexpr int XBLK = 2048;         // x elements converted per prologue block
}

// ---------------- device scratch --------------------------------------------
__device__ __half g_x_hf[MAXROWS * E];   // 64MB
__device__ __half g_c_hf[KC * E];        // 4MB
__device__ __align__(16) __half g_D[(size_t)MAXROWS * KC]; // 131MB dists - DOFF
__device__ float  g_cnorm[KC];

// ---------------- helpers ----------------------------------------------------
DINLINE uint32_t smem_u32(const void* p) {
    uint32_t a;
    asm("{ .reg .u64 t; cvta.to.shared.u64 t, %1; cvt.u32.u64 %0, t; }"
        : "=r"(a) : "l"(p));
    return a;
}
DINLINE uint32_t sw128(uint32_t o) { return o ^ ((o >> 3) & 0x70); }
DINLINE uint32_t swz(uint32_t rel) {           // 1024-aligned region swizzle
    return (rel & ~1023u) | sw128(rel & 1023u);
}

DINLINE void cp16(uint32_t dst, const void* src) {
    asm volatile("cp.async.cg.shared.global [%0], [%1], 16;"
                 :: "r"(dst), "l"(src) : "memory");
}
#define CP_COMMIT()      asm volatile("cp.async.commit_group;" ::: "memory")
#define CP_WAIT_GROUP(n) asm volatile("cp.async.wait_group %0;" :: "n"(n) : "memory")

DINLINE void ldm_x4(uint32_t& r0, uint32_t& r1, uint32_t& r2, uint32_t& r3,
                    uint32_t addr) {
    asm volatile("ldmatrix.sync.aligned.m8n8.x4.shared.b16 {%0,%1,%2,%3}, [%4];"
                 : "=r"(r0), "=r"(r1), "=r"(r2), "=r"(r3) : "r"(addr));
}
// all-f16 MMA: D(f16) = A(f16)*B(f16) + C(f16); 2 regs for D/C
DINLINE void mma_f16(uint32_t& d0, uint32_t& d1,
                     uint32_t a0, uint32_t a1, uint32_t a2, uint32_t a3,
                     uint32_t b0, uint32_t b1) {
    asm volatile("mma.sync.aligned.m16n8k16.row.col.f16.f16.f16.f16 "
                 "{%0,%1}, {%2,%3,%4,%5}, {%6,%7}, {%0,%1};"
                 : "+r"(d0), "+r"(d1)
                 : "r"(a0), "r"(a1), "r"(a2), "r"(a3), "r"(b0), "r"(b1));
}

// ---------------- merged prologue: convert x + convert c + cnorm -------------
__global__ void prologue_kernel(const float* __restrict__ x,
                                const float* __restrict__ cen, int nxb) {
    const int tid = threadIdx.x;
    if (blockIdx.x < nxb) {
        const size_t base = (size_t)blockIdx.x * XBLK + (size_t)tid * 8;
        const float4* s4 = reinterpret_cast<const float4*>(x + base);
        float4 a = s4[0], b = s4[1];
        float v[8] = {a.x, a.y, a.z, a.w, b.x, b.y, b.z, b.w};
        uint4 o;
        __half* p = reinterpret_cast<__half*>(&o);
        #pragma unroll
        for (int j = 0; j < 8; j++) p[j] = __float2half_rn(v[j]);
        *reinterpret_cast<uint4*>(g_x_hf + base) = o;
    } else {
        const int row = blockIdx.x - nxb;
        const float4 a = reinterpret_cast<const float4*>(cen + (size_t)row * E)[tid];
        float v[4] = {a.x, a.y, a.z, a.w};
        uint2 o;
        __half* p = reinterpret_cast<__half*>(&o);
        float s = 0.f;
        #pragma unroll
        for (int j = 0; j < 4; j++) {
            p[j] = __float2half_rn(v[j]);
            s = fmaf(v[j], v[j], s);
        }
        *reinterpret_cast<uint2*>(g_c_hf + (size_t)row * E + tid * 4) = o;

        __shared__ float sm[8];
        #pragma unroll
        for (int off = 16; off > 0; off >>= 1)
            s += __shfl_down_sync(0xffffffffu, s, off);
        if ((tid & 31) == 0) sm[tid >> 5] = s;
        __syncthreads();
        if (tid < 8) {
            s = sm[tid];
            #pragma unroll
            for (int off = 4; off > 0; off >>= 1)
                s += __shfl_down_sync(0xffu, s, off);
            if (tid == 0) g_cnorm[row] = s;
        }
    }
}

// ---------------- GEMM (fp16 in, fp16 acc): D = cnorm - 2*x.c - DOFF ---------
DINLINE void fill_stage(int kt, int row0, int n0, int tid, uint32_t sbase) {
    const uint32_t soff = (uint32_t)(kt & (NSTAGE - 1)) * STAGE_BYTES;
    const int r    = tid >> 1;          // 0..127
    const int half = tid & 1;           // k bytes 0-63 / 64-127
    const int k0   = kt * BK + half * 32;
    const uint32_t rowrel = (uint32_t)r * 128u + (uint32_t)half * 64u;
    #pragma unroll
    for (int pass = 0; pass < 2; pass++) {  // A: 256 rows
        const __half* xs = g_x_hf + (size_t)(row0 + pass * 128 + r) * E + k0;
        const uint32_t abase = soff + (uint32_t)pass * 16384u + rowrel;
        #pragma unroll
        for (int q = 0; q < 4; q++)
            cp16(sbase + swz(abase + q * 16u), xs + q * 8);
    }
    const __half* cs = g_c_hf + (size_t)(n0 + r) * E + k0;   // B: 128 rows
    const uint32_t bbase = soff + (uint32_t)OFF_B + rowrel;
    #pragma unroll
    for (int q = 0; q < 4; q++)
        cp16(sbase + swz(bbase + q * 16u), cs + q * 8);
}

__global__ void __launch_bounds__(GTHREADS, 2)
gemm_f16_kernel() {
    extern __shared__ __align__(1024) char smem[];
    const uint32_t sbase = smem_u32(smem);
    const int tid  = threadIdx.x;
    const int lane = tid & 31;
    const int wid  = tid >> 5;
    const int wm   = wid & 3;           // warp m: 0..3 (64 rows each)
    const int wn   = wid >> 2;          // warp n: 0..1 (64 cols each)
    const int n0   = blockIdx.x * BN;
    const int row0 = blockIdx.y * BM;

    float* s_cnorm = reinterpret_cast<float*>(smem + OFF_CNORM);
    if (tid < BN) s_cnorm[tid] = g_cnorm[n0 + tid];

    uint32_t acc[4][8][2];              // fp16x2 accumulators
    #pragma unroll
    for (int mt = 0; mt < 4; mt++)
        #pragma unroll
        for (int nt = 0; nt < 8; nt++) { acc[mt][nt][0] = 0u; acc[mt][nt][1] = 0u; }

    fill_stage(0, row0, n0, tid, sbase); CP_COMMIT();
    fill_stage(1, row0, n0, tid, sbase); CP_COMMIT();

    const int lrow16 = lane & 15;
    const int lksel  = lane >> 4;
    const int bgrp   = lane >> 3;
    const int brow   = lane & 7;

    for (int kt = 0; kt < NK; kt++) {
        CP_WAIT_GROUP(1);               // stage kt resident
        __syncthreads();

        const uint32_t sa = sbase + (uint32_t)(kt & (NSTAGE - 1)) * STAGE_BYTES;
        const uint32_t sb = sa + OFF_B;

        #pragma unroll
        for (int ks = 0; ks < 4; ks++) {
            const uint32_t kb = (uint32_t)ks * 32u;
            // B frags (4 ldsm -> 8 n-tiles)
            uint32_t bF[8][2];
            #pragma unroll
            for (int np = 0; np < 4; np++) {
                uint32_t n = (uint32_t)(wn * 64 + (np * 2 + (bgrp >> 1)) * 8 + brow);
                uint32_t addr = sb + swz(n * 128u + kb + (uint32_t)(bgrp & 1) * 16u);
                uint32_t r0, r1, r2, r3;
                ldm_x4(r0, r1, r2, r3, addr);
                bF[np * 2][0] = r0; bF[np * 2][1] = r1;
                bF[np * 2 + 1][0] = r2; bF[np * 2 + 1][1] = r3;
            }
            // A frags (4 m-subtiles x 16 rows)
            uint32_t aF[4][4];
            #pragma unroll
            for (int mt = 0; mt < 4; mt++) {
                uint32_t r = (uint32_t)(wm * 64 + mt * 16 + lrow16);
                uint32_t addr = sa + swz(r * 128u + kb + (uint32_t)lksel * 16u);
                ldm_x4(aF[mt][0], aF[mt][1], aF[mt][2], aF[mt][3], addr);
            }
            #pragma unroll
            for (int mt = 0; mt < 4; mt++)
                #pragma unroll
                for (int nt = 0; nt < 8; nt++)
                    mma_f16(acc[mt][nt][0], acc[mt][nt][1],
                            aF[mt][0], aF[mt][1], aF[mt][2], aF[mt][3],
                            bF[nt][0], bF[nt][1]);
        }

        __syncthreads();                // reads of slot kt%2 done
        if (kt + 2 < NK) fill_stage(kt + 2, row0, n0, tid, sbase);
        CP_COMMIT();                    // uniform group accounting
    }

    // epilogue: d = cnorm[n] - 2*dot - DOFF, fp16 store
    const int lr = lane >> 2;           // 0..7
    const int lc = (lane & 3) * 2;
    #pragma unroll
    for (int mt = 0; mt < 4; mt++) {
        #pragma unroll
        for (int half = 0; half < 2; half++) {   // reg0: row lr, reg1: row lr+8
            const int row = wm * 64 + mt * 16 + lr + half * 8;
            __half* drow = g_D + (size_t)(row0 + row) * KC + n0;
            #pragma unroll
            for (int nt = 0; nt < 8; nt++) {
                const int col = wn * 64 + nt * 8 + lc;
                float2 dot = __half22float2(
                    *reinterpret_cast<const __half2*>(&acc[mt][nt][half]));
                float dx = fmaf(-2.f, dot.x, s_cnorm[col])     - DOFF;
                float dy = fmaf(-2.f, dot.y, s_cnorm[col + 1]) - DOFF;
                *reinterpret_cast<__half2*>(drow + col) = __floats2half2_rn(dx, dy);
            }
        }
    }
}

// ---------------- refine: warp-per-row scan + exact fp32 recheck -------------
__global__ void __launch_bounds__(256)
refine_kernel(const float* __restrict__ x, const float* __restrict__ cen,
              float* __restrict__ out) {
    const int lane = threadIdx.x & 31;
    const int w    = threadIdx.x >> 5;
    const int row  = blockIdx.x * 8 + w;

    __shared__ int s_cand[8][CAP];
    __shared__ int s_cnt[8];
    if (lane == 0) s_cnt[w] = 0;
    __syncwarp();

    const uint4* dr = reinterpret_cast<const uint4*>(g_D + (size_t)row * KC);
    // pass 1: min (8 x uint4 per lane = 2048 halves per warp)
    float mn = 3.4e38f;
    #pragma unroll
    for (int j = 0; j < 8; j++) {
        uint4 p = dr[lane + 32 * j];
        const __half2* h2 = reinterpret_cast<const __half2*>(&p);
        #pragma unroll
        for (int q = 0; q < 4; q++) {
            float2 f = __half22float2(h2[q]);
            mn = fminf(mn, fminf(f.x, f.y));
        }
    }
    #pragma unroll
    for (int o = 16; o > 0; o >>= 1)
        mn = fminf(mn, __shfl_xor_sync(0xffffffffu, mn, o));
    const float th = mn + MARGIN;

    // pass 2 (L1-hot): collect candidates
    #pragma unroll
    for (int j = 0; j < 8; j++) {
        uint4 p = dr[lane + 32 * j];
        const __half2* h2 = reinterpret_cast<const __half2*>(&p);
        #pragma unroll
        for (int q = 0; q < 4; q++) {
            float2 f = __half22float2(h2[q]);
            if (f.x <= th) {
                int s = atomicAdd(&s_cnt[w], 1);
                if (s < CAP) s_cand[w][s] = (lane + 32 * j) * 8 + q * 2;
            }
            if (f.y <= th) {
                int s = atomicAdd(&s_cnt[w], 1);
                if (s < CAP) s_cand[w][s] = (lane + 32 * j) * 8 + q * 2 + 1;
            }
        }
    }
    __syncwarp();
    const int cnt = min(s_cnt[w], CAP);

    if (cnt == 1) {                 // single candidate: it is the argmin
        if (lane == 0) out[row] = (float)s_cand[w][0];
        return;
    }

    // exact fp32 recheck (warp-cooperative dot per candidate)
    const float4* xr = reinterpret_cast<const float4*>(x + (size_t)row * E);
    float4 xa[8];
    #pragma unroll
    for (int j = 0; j < 8; j++) xa[j] = xr[lane + 32 * j];

    float best_d = 3.4e38f;
    int   best_i = 0x7fffffff;
    for (int i = 0; i < cnt; i++) {
        const int c = s_cand[w][i];
        const float4* cr = reinterpret_cast<const float4*>(cen + (size_t)c * E);
        float p = 0.f;
        #pragma unroll
        for (int j = 0; j < 8; j++) {
            float4 b = cr[lane + 32 * j];
            p = fmaf(xa[j].x, b.x, p); p = fmaf(xa[j].y, b.y, p);
            p = fmaf(xa[j].z, b.z, p); p = fmaf(xa[j].w, b.w, p);
        }
        #pragma unroll
        for (int o = 16; o > 0; o >>= 1)
            p += __shfl_xor_sync(0xffffffffu, p, o);
        const float dd = fmaf(-2.f, p, g_cnorm[c]);
        if (dd < best_d || (dd == best_d && c < best_i)) { best_d = dd; best_i = c; }
    }
    if (lane == 0) out[row] = (float)best_i;
}

// ---------------- launch ------------------------------------------------------
extern "C" void kernel_launch(void* const* d_in, const int* in_sizes, int n_in,
                              void* d_out, int out_size) {
    const float* a0 = (const float*)d_in[0];
    const float* a1 = (const float*)d_in[1];
    const float* x;
    const float* cen;
    if (in_sizes[0] >= in_sizes[1]) { x = a0; cen = a1; }
    else                            { x = a1; cen = a0; }

    float* out = (float*)d_out;
    const int nrows = out_size;                  // 32000

    const int nxb = nrows * E / XBLK;            // 16000
    prologue_kernel<<<nxb + KC, 256>>>(x, cen, nxb);

    cudaFuncSetAttribute(gemm_f16_kernel,
                         cudaFuncAttributeMaxDynamicSharedMemorySize, GSMEM_TOTAL);
    dim3 ggrid(KC / BN, nrows / BM);             // (16, 125)
    gemm_f16_kernel<<<ggrid, GTHREADS, GSMEM_TOTAL>>>();

    refine_kernel<<<nrows / 8, 256>>>(x, cen, out);
}

// round 13
// speedup vs baseline: 1.0686x; 1.0081x over previous
#include <cuda_runtime.h>
#include <cuda_fp16.h>
#include <cstdint>
#include <cstddef>

#define DINLINE __device__ __forceinline__

namespace {
constexpr int E       = 1024;
constexpr int KC      = 2048;
constexpr int MAXROWS = 32000;

constexpr int BM = 256;          // CTA rows
constexpr int BN = 128;          // CTA centroids
constexpr int BK = 64;           // k-chunk (64 fp16 = 128B row, SW128-friendly)
constexpr int NK = E / BK;       // 16
constexpr int NSTAGE = 2;
constexpr int GTHREADS = 256;    // 8 warps: 4(m) x 2(n), warp tile 64x64

constexpr int STAGE_BYTES = (BM + BN) * BK * 2;     // 48KB
constexpr int OFF_B       = BM * BK * 2;            // 32KB: B after A in stage
constexpr int OFF_CNORM   = NSTAGE * STAGE_BYTES;   // 96KB
constexpr int GSMEM_TOTAL = OFF_CNORM + BN * 4;     // 98816 -> 2 CTAs/SM

constexpr float DOFF   = 2048.0f;  // center dists before fp16 store
constexpr float MARGIN = 10.0f;    // >> fp16-acc err (~4) + fp16 quant (~0.5)
constexpr int   CAP    = 128;      // candidate cap per row
constexpr int   NCHK   = 32;       // 64-col min-chunks per row (2048/64)

constexpr int XBLK = 2048;         // x elements converted per prologue block
}

// ---------------- device scratch --------------------------------------------
__device__ __half g_x_hf[MAXROWS * E];   // 64MB
__device__ __half g_c_hf[KC * E];        // 4MB
__device__ __align__(16) __half g_D[(size_t)MAXROWS * KC]; // 131MB dists - DOFF
__device__ float  g_pmin[(size_t)MAXROWS * NCHK];          // 4MB per-chunk mins
__device__ float  g_cnorm[KC];

// ---------------- helpers ----------------------------------------------------
DINLINE uint32_t smem_u32(const void* p) {
    uint32_t a;
    asm("{ .reg .u64 t; cvta.to.shared.u64 t, %1; cvt.u32.u64 %0, t; }"
        : "=r"(a) : "l"(p));
    return a;
}
DINLINE uint32_t sw128(uint32_t o) { return o ^ ((o >> 3) & 0x70); }
DINLINE uint32_t swz(uint32_t rel) {           // 1024-aligned region swizzle
    return (rel & ~1023u) | sw128(rel & 1023u);
}

DINLINE void cp16(uint32_t dst, const void* src) {
    asm volatile("cp.async.cg.shared.global [%0], [%1], 16;"
                 :: "r"(dst), "l"(src) : "memory");
}
#define CP_COMMIT()      asm volatile("cp.async.commit_group;" ::: "memory")
#define CP_WAIT_GROUP(n) asm volatile("cp.async.wait_group %0;" :: "n"(n) : "memory")

DINLINE void ldm_x4(uint32_t& r0, uint32_t& r1, uint32_t& r2, uint32_t& r3,
                    uint32_t addr) {
    asm volatile("ldmatrix.sync.aligned.m8n8.x4.shared.b16 {%0,%1,%2,%3}, [%4];"
                 : "=r"(r0), "=r"(r1), "=r"(r2), "=r"(r3) : "r"(addr));
}
// all-f16 MMA: D(f16) = A(f16)*B(f16) + C(f16); 2 regs for D/C
DINLINE void mma_f16(uint32_t& d0, uint32_t& d1,
                     uint32_t a0, uint32_t a1, uint32_t a2, uint32_t a3,
                     uint32_t b0, uint32_t b1) {
    asm volatile("mma.sync.aligned.m16n8k16.row.col.f16.f16.f16.f16 "
                 "{%0,%1}, {%2,%3,%4,%5}, {%6,%7}, {%0,%1};"
                 : "+r"(d0), "+r"(d1)
                 : "r"(a0), "r"(a1), "r"(a2), "r"(a3), "r"(b0), "r"(b1));
}

// ---------------- merged prologue: convert x + convert c + cnorm -------------
__global__ void prologue_kernel(const float* __restrict__ x,
                                const float* __restrict__ cen, int nxb) {
    const int tid = threadIdx.x;
    if (blockIdx.x < nxb) {
        const size_t base = (size_t)blockIdx.x * XBLK + (size_t)tid * 8;
        const float4* s4 = reinterpret_cast<const float4*>(x + base);
        float4 a = s4[0], b = s4[1];
        float v[8] = {a.x, a.y, a.z, a.w, b.x, b.y, b.z, b.w};
        uint4 o;
        __half* p = reinterpret_cast<__half*>(&o);
        #pragma unroll
        for (int j = 0; j < 8; j++) p[j] = __float2half_rn(v[j]);
        *reinterpret_cast<uint4*>(g_x_hf + base) = o;
    } else {
        const int row = blockIdx.x - nxb;
        const float4 a = reinterpret_cast<const float4*>(cen + (size_t)row * E)[tid];
        float v[4] = {a.x, a.y, a.z, a.w};
        uint2 o;
        __half* p = reinterpret_cast<__half*>(&o);
        float s = 0.f;
        #pragma unroll
        for (int j = 0; j < 4; j++) {
            p[j] = __float2half_rn(v[j]);
            s = fmaf(v[j], v[j], s);
        }
        *reinterpret_cast<uint2*>(g_c_hf + (size_t)row * E + tid * 4) = o;

        __shared__ float sm[8];
        #pragma unroll
        for (int off = 16; off > 0; off >>= 1)
            s += __shfl_down_sync(0xffffffffu, s, off);
        if ((tid & 31) == 0) sm[tid >> 5] = s;
        __syncthreads();
        if (tid < 8) {
            s = sm[tid];
            #pragma unroll
            for (int off = 4; off > 0; off >>= 1)
                s += __shfl_down_sync(0xffu, s, off);
            if (tid == 0) g_cnorm[row] = s;
        }
    }
}

// ---------------- GEMM (fp16 in, fp16 acc): D = cnorm - 2*x.c - DOFF ---------
DINLINE void fill_stage(int kt, int row0, int n0, int tid, uint32_t sbase) {
    const uint32_t soff = (uint32_t)(kt & (NSTAGE - 1)) * STAGE_BYTES;
    const int r    = tid >> 1;          // 0..127
    const int half = tid & 1;           // k bytes 0-63 / 64-127
    const int k0   = kt * BK + half * 32;
    const uint32_t rowrel = (uint32_t)r * 128u + (uint32_t)half * 64u;
    #pragma unroll
    for (int pass = 0; pass < 2; pass++) {  // A: 256 rows
        const __half* xs = g_x_hf + (size_t)(row0 + pass * 128 + r) * E + k0;
        const uint32_t abase = soff + (uint32_t)pass * 16384u + rowrel;
        #pragma unroll
        for (int q = 0; q < 4; q++)
            cp16(sbase + swz(abase + q * 16u), xs + q * 8);
    }
    const __half* cs = g_c_hf + (size_t)(n0 + r) * E + k0;   // B: 128 rows
    const uint32_t bbase = soff + (uint32_t)OFF_B + rowrel;
    #pragma unroll
    for (int q = 0; q < 4; q++)
        cp16(sbase + swz(bbase + q * 16u), cs + q * 8);
}

__global__ void __launch_bounds__(GTHREADS, 2)
gemm_f16_kernel() {
    extern __shared__ __align__(1024) char smem[];
    const uint32_t sbase = smem_u32(smem);
    const int tid  = threadIdx.x;
    const int lane = tid & 31;
    const int wid  = tid >> 5;
    const int wm   = wid & 3;           // warp m: 0..3 (64 rows each)
    const int wn   = wid >> 2;          // warp n: 0..1 (64 cols each)
    const int n0   = blockIdx.x * BN;
    const int row0 = blockIdx.y * BM;

    float* s_cnorm = reinterpret_cast<float*>(smem + OFF_CNORM);
    if (tid < BN) s_cnorm[tid] = g_cnorm[n0 + tid];

    uint32_t acc[4][8][2];              // fp16x2 accumulators
    #pragma unroll
    for (int mt = 0; mt < 4; mt++)
        #pragma unroll
        for (int nt = 0; nt < 8; nt++) { acc[mt][nt][0] = 0u; acc[mt][nt][1] = 0u; }

    fill_stage(0, row0, n0, tid, sbase); CP_COMMIT();
    fill_stage(1, row0, n0, tid, sbase); CP_COMMIT();

    const int lrow16 = lane & 15;
    const int lksel  = lane >> 4;
    const int bgrp   = lane >> 3;
    const int brow   = lane & 7;

    for (int kt = 0; kt < NK; kt++) {
        CP_WAIT_GROUP(1);               // stage kt resident
        __syncthreads();

        const uint32_t sa = sbase + (uint32_t)(kt & (NSTAGE - 1)) * STAGE_BYTES;
        const uint32_t sb = sa + OFF_B;

        #pragma unroll
        for (int ks = 0; ks < 4; ks++) {
            const uint32_t kb = (uint32_t)ks * 32u;
            // B frags (4 ldsm -> 8 n-tiles)
            uint32_t bF[8][2];
            #pragma unroll
            for (int np = 0; np < 4; np++) {
                uint32_t n = (uint32_t)(wn * 64 + (np * 2 + (bgrp >> 1)) * 8 + brow);
                uint32_t addr = sb + swz(n * 128u + kb + (uint32_t)(bgrp & 1) * 16u);
                uint32_t r0, r1, r2, r3;
                ldm_x4(r0, r1, r2, r3, addr);
                bF[np * 2][0] = r0; bF[np * 2][1] = r1;
                bF[np * 2 + 1][0] = r2; bF[np * 2 + 1][1] = r3;
            }
            // A frags (4 m-subtiles x 16 rows)
            uint32_t aF[4][4];
            #pragma unroll
            for (int mt = 0; mt < 4; mt++) {
                uint32_t r = (uint32_t)(wm * 64 + mt * 16 + lrow16);
                uint32_t addr = sa + swz(r * 128u + kb + (uint32_t)lksel * 16u);
                ldm_x4(aF[mt][0], aF[mt][1], aF[mt][2], aF[mt][3], addr);
            }
            #pragma unroll
            for (int mt = 0; mt < 4; mt++)
                #pragma unroll
                for (int nt = 0; nt < 8; nt++)
                    mma_f16(acc[mt][nt][0], acc[mt][nt][1],
                            aF[mt][0], aF[mt][1], aF[mt][2], aF[mt][3],
                            bF[nt][0], bF[nt][1]);
        }

        __syncthreads();                // reads of slot kt%2 done
        if (kt + 2 < NK) fill_stage(kt + 2, row0, n0, tid, sbase);
        CP_COMMIT();                    // uniform group accounting
    }

    // epilogue: d = cnorm[n] - 2*dot - DOFF; fp16 store + per-row 64-col min
    const int lr = lane >> 2;           // 0..7
    const int lc = (lane & 3) * 2;
    #pragma unroll
    for (int mt = 0; mt < 4; mt++) {
        #pragma unroll
        for (int half = 0; half < 2; half++) {   // reg0: row lr, reg1: row lr+8
            const int row = wm * 64 + mt * 16 + lr + half * 8;
            __half* drow = g_D + (size_t)(row0 + row) * KC + n0;
            float mn = 3.4e38f;
            #pragma unroll
            for (int nt = 0; nt < 8; nt++) {
                const int col = wn * 64 + nt * 8 + lc;
                float2 dot = __half22float2(
                    *reinterpret_cast<const __half2*>(&acc[mt][nt][half]));
                float dx = fmaf(-2.f, dot.x, s_cnorm[col])     - DOFF;
                float dy = fmaf(-2.f, dot.y, s_cnorm[col + 1]) - DOFF;
                *reinterpret_cast<__half2*>(drow + col) = __floats2half2_rn(dx, dy);
                mn = fminf(mn, fminf(dx, dy));
            }
            // min across the 4 lanes covering this row's 64 cols
            mn = fminf(mn, __shfl_xor_sync(0xffffffffu, mn, 1));
            mn = fminf(mn, __shfl_xor_sync(0xffffffffu, mn, 2));
            if ((lane & 3) == 0)
                g_pmin[(size_t)(row0 + row) * NCHK + blockIdx.x * 2 + wn] = mn;
        }
    }
}

// ---------------- refine: pmin triage -> hot-chunk scan -> exact recheck -----
__global__ void __launch_bounds__(256)
refine_kernel(const float* __restrict__ x, const float* __restrict__ cen,
              float* __restrict__ out) {
    const int lane = threadIdx.x & 31;
    const int w    = threadIdx.x >> 5;
    const int row  = blockIdx.x * 8 + w;

    __shared__ int s_cand[8][CAP];
    __shared__ int s_cnt[8];
    if (lane == 0) s_cnt[w] = 0;
    __syncwarp();

    // 1) per-chunk mins: one per lane
    const float pm = g_pmin[(size_t)row * NCHK + lane];
    float gmin = pm;
    #pragma unroll
    for (int o = 16; o > 0; o >>= 1)
        gmin = fminf(gmin, __shfl_xor_sync(0xffffffffu, gmin, o));
    const float th = gmin + MARGIN;
    unsigned chunkmask = __ballot_sync(0xffffffffu, pm <= th);

    // 2) scan only hot 64-col chunks (usually exactly one)
    while (chunkmask) {
        const int j = __ffs(chunkmask) - 1;
        chunkmask &= chunkmask - 1;
        const __half2 hv = reinterpret_cast<const __half2*>(
            g_D + (size_t)row * KC + j * 64)[lane];
        const float2 f = __half22float2(hv);
        if (f.x <= th) {
            int s = atomicAdd(&s_cnt[w], 1);
            if (s < CAP) s_cand[w][s] = j * 64 + lane * 2;
        }
        if (f.y <= th) {
            int s = atomicAdd(&s_cnt[w], 1);
            if (s < CAP) s_cand[w][s] = j * 64 + lane * 2 + 1;
        }
    }
    __syncwarp();
    const int cnt = min(s_cnt[w], CAP);

    if (cnt == 1) {                 // single candidate: it is the argmin
        if (lane == 0) out[row] = (float)s_cand[w][0];
        return;
    }

    // 3) exact fp32 recheck (warp-cooperative dot per candidate)
    const float4* xr = reinterpret_cast<const float4*>(x + (size_t)row * E);
    float4 xa[8];
    #pragma unroll
    for (int j = 0; j < 8; j++) xa[j] = xr[lane + 32 * j];

    float best_d = 3.4e38f;
    int   best_i = 0x7fffffff;
    for (int i = 0; i < cnt; i++) {
        const int c = s_cand[w][i];
        const float4* cr = reinterpret_cast<const float4*>(cen + (size_t)c * E);
        float p = 0.f;
        #pragma unroll
        for (int j = 0; j < 8; j++) {
            float4 b = cr[lane + 32 * j];
            p = fmaf(xa[j].x, b.x, p); p = fmaf(xa[j].y, b.y, p);
            p = fmaf(xa[j].z, b.z, p); p = fmaf(xa[j].w, b.w, p);
        }
        #pragma unroll
        for (int o = 16; o > 0; o >>= 1)
            p += __shfl_xor_sync(0xffffffffu, p, o);
        const float dd = fmaf(-2.f, p, g_cnorm[c]);
        if (dd < best_d || (dd == best_d && c < best_i)) { best_d = dd; best_i = c; }
    }
    if (lane == 0) out[row] = (float)best_i;
}

// ---------------- launch ------------------------------------------------------
extern "C" void kernel_launch(void* const* d_in, const int* in_sizes, int n_in,
                              void* d_out, int out_size) {
    const float* a0 = (const float*)d_in[0];
    const float* a1 = (const float*)d_in[1];
    const float* x;
    const float* cen;
    if (in_sizes[0] >= in_sizes[1]) { x = a0; cen = a1; }
    else                            { x = a1; cen = a0; }

    float* out = (float*)d_out;
    const int nrows = out_size;                  // 32000

    const int nxb = nrows * E / XBLK;            // 16000
    prologue_kernel<<<nxb + KC, 256>>>(x, cen, nxb);

    cudaFuncSetAttribute(gemm_f16_kernel,
                         cudaFuncAttributeMaxDynamicSharedMemorySize, GSMEM_TOTAL);
    dim3 ggrid(KC / BN, nrows / BM);             // (16, 125)
    gemm_f16_kernel<<<ggrid, GTHREADS, GSMEM_TOTAL>>>();

    refine_kernel<<<nrows / 8, 256>>>(x, cen, out);
}